// round 1
// baseline (speedup 1.0000x reference)
#include <cuda_runtime.h>
#include <cstdint>

// Problem constants (fixed shapes from reference setup_inputs)
#define B_TOTAL 262144
#define NIN 66      // input features
#define NE  50      // E_NODE
#define NA  20      // A_NODE
#define ROWS 256    // rows per block
#define XPITCH 67   // x tile pitch (67 mod 32 odd-ish -> conflict-free strided access)

// ---------------------------------------------------------------------------
// Packed f32x2 helpers (Blackwell sm_100a+): doubles fp32 FMA throughput vs
// 3-reg FFMA (rt_SMSP=2 -> 64 lanes/cyc/SM scalar; f32x2 packs 2 lanes/op).
// ---------------------------------------------------------------------------
__device__ __forceinline__ unsigned long long dup2(float v) {
    unsigned long long r;
    asm("mov.b64 %0, {%1, %1};" : "=l"(r) : "f"(v));
    return r;
}
__device__ __forceinline__ void fma2(unsigned long long& d,
                                     unsigned long long a,
                                     unsigned long long b) {
    asm("fma.rn.f32x2 %0, %1, %2, %0;" : "+l"(d) : "l"(a), "l"(b));
}
__device__ __forceinline__ float lo32(unsigned long long v) {
    return __uint_as_float((unsigned)v);
}
__device__ __forceinline__ float hi32(unsigned long long v) {
    return __uint_as_float((unsigned)(v >> 32));
}

__device__ __forceinline__ void cp16(void* smem, const void* g) {
    uint32_t s = (uint32_t)__cvta_generic_to_shared(smem);
    asm volatile("cp.async.ca.shared.global [%0], [%1], 16;" :: "r"(s), "l"(g));
}

// ---------------------------------------------------------------------------
// One block = 256 rows of x. Per thread = one row.
//  Phase 1: E[50] = tanh(x_row @ E_W + E_b)      (f32x2, EW broadcast from smem)
//  Phase 2: for each i in 0..65:
//             s[20] = E @ A_W[i] + A_b[i]        (f32x2, A_W[i] dbl-buffered cp.async)
//             A     = 1 / sum_a exp(s[a]-s[1])   (softmax class-1 prob, max-free)
//             x_sh[row][i] *= A                  (in-place; coalesced writeback at end)
// ---------------------------------------------------------------------------
__global__ void __launch_bounds__(256, 2)
attn_kernel(const float* __restrict__ x,  const float* __restrict__ EW,
            const float* __restrict__ Eb, const float* __restrict__ AW,
            const float* __restrict__ Ab, float* __restrict__ out)
{
    extern __shared__ float sh[];
    float* x_sh  = sh;                        // ROWS*XPITCH = 17152 floats
    float* ew_sh = x_sh + ROWS * XPITCH;      // 66*50 = 3300
    float* ab_sh = ew_sh + NIN * NE;          // 66*20 = 1320
    float* w_sh  = ab_sh + NIN * NA;          // 2*1000 (double buffer), 16B aligned

    const int tid = threadIdx.x;
    const long long base = (long long)blockIdx.x * ROWS;

    // Stage A_W[0], A_W[1] early so the LDGSTS overlaps the scalar staging below.
    if (tid < 250) cp16(w_sh + tid * 4, AW + tid * 4);
    asm volatile("cp.async.commit_group;");
    if (tid < 250) cp16(w_sh + 1000 + tid * 4, AW + 1000 + tid * 4);
    asm volatile("cp.async.commit_group;");

    // Coalesced tile loads.
    const float* xg = x + base * NIN;
    for (int idx = tid; idx < ROWS * NIN; idx += 256)
        x_sh[(idx / NIN) * XPITCH + (idx % NIN)] = xg[idx];
    for (int idx = tid; idx < NIN * NE; idx += 256) ew_sh[idx] = EW[idx];
    for (int idx = tid; idx < NIN * NA; idx += 256) ab_sh[idx] = Ab[idx];
    __syncthreads();

    // ------------------ Phase 1: E = tanh(x @ E_W + E_b) ------------------
    const float* xr = x_sh + tid * XPITCH;
    unsigned long long eacc[NE / 2];
#pragma unroll
    for (int p = 0; p < NE / 2; ++p) eacc[p] = 0ULL;

#pragma unroll 1
    for (int i = 0; i < NIN; ++i) {
        unsigned long long x2 = dup2(xr[i]);
        const unsigned long long* w =
            reinterpret_cast<const unsigned long long*>(ew_sh + i * NE);
#pragma unroll
        for (int p = 0; p < NE / 2; ++p) fma2(eacc[p], x2, w[p]);
    }

    float E[NE];
#pragma unroll
    for (int p = 0; p < NE / 2; ++p) {
        E[2 * p]     = tanhf(lo32(eacc[p]) + __ldg(Eb + 2 * p));
        E[2 * p + 1] = tanhf(hi32(eacc[p]) + __ldg(Eb + 2 * p + 1));
    }

    // ------------------ Phase 2: per-feature attention --------------------
    float* xw = x_sh + tid * XPITCH;
#pragma unroll 1
    for (int i = 0; i < NIN; ++i) {
        asm volatile("cp.async.wait_group 1;");   // A_W[i] resident
        __syncthreads();

        const float* W = w_sh + (i & 1) * 1000;
        unsigned long long acc[NA / 2];
        const unsigned long long* ab =
            reinterpret_cast<const unsigned long long*>(ab_sh + i * NA);
#pragma unroll
        for (int p = 0; p < NA / 2; ++p) acc[p] = ab[p];

#pragma unroll
        for (int e = 0; e < NE; ++e) {
            unsigned long long e2 = dup2(E[e]);
            const ulonglong2* we =
                reinterpret_cast<const ulonglong2*>(W + e * NA);  // 16B aligned
#pragma unroll
            for (int q = 0; q < 5; ++q) {
                ulonglong2 wv = we[q];                // LDS.128 broadcast
                fma2(acc[2 * q],     e2, wv.x);
                fma2(acc[2 * q + 1], e2, wv.y);
            }
        }

        // Softmax over 20 classes; keep class 1. Max-free: denom >= exp(0)=1.
        float s1 = hi32(acc[0]);
        float denom = 0.0f;
#pragma unroll
        for (int p = 0; p < NA / 2; ++p) {
            denom += __expf(lo32(acc[p]) - s1);
            denom += __expf(hi32(acc[p]) - s1);
        }
        float Ap = __fdividef(1.0f, denom);
        xw[i] = xr[i] * Ap;                   // in-place: x no longer needed at i

        __syncthreads();                      // all readers done with buf (i&1)
        if (i + 2 < NIN) {                    // prefetch A_W[i+2] into freed buf
            if (tid < 250)
                cp16(w_sh + (i & 1) * 1000 + tid * 4, AW + (i + 2) * 1000 + tid * 4);
        }
        asm volatile("cp.async.commit_group;");  // commit (possibly empty) group
    }

    // Coalesced writeback.
    __syncthreads();
    float* og = out + base * NIN;
    for (int idx = tid; idx < ROWS * NIN; idx += 256)
        og[idx] = x_sh[(idx / NIN) * XPITCH + (idx % NIN)];
}

extern "C" void kernel_launch(void* const* d_in, const int* in_sizes, int n_in,
                              void* d_out, int out_size) {
    const float* x  = (const float*)d_in[0];
    const float* EW = (const float*)d_in[1];
    const float* Eb = (const float*)d_in[2];
    const float* AW = (const float*)d_in[3];
    const float* Ab = (const float*)d_in[4];
    float* out = (float*)d_out;

    const size_t smem = (ROWS * XPITCH + NIN * NE + NIN * NA + 2000) * sizeof(float);
    cudaFuncSetAttribute(attn_kernel,
                         cudaFuncAttributeMaxDynamicSharedMemorySize, (int)smem);
    attn_kernel<<<B_TOTAL / ROWS, 256, smem>>>(x, EW, Eb, AW, Ab, out);
}

// round 2
// speedup vs baseline: 1.1051x; 1.1051x over previous
#include <cuda_runtime.h>
#include <cstdint>

// Problem constants (fixed shapes from reference setup_inputs)
#define B_TOTAL 262144
#define NIN 66      // input features
#define NE  50      // E_NODE
#define NA  20      // A_NODE
#define THREADS 128
#define ROWS 256    // rows per block; R = 2 rows per thread (t and t+128)
#define XPITCH 67   // x tile pitch: 67 mod 32 = 3 -> conflict-free per-row access

// Shared layout (float offsets)
#define OFF_X   0
#define OFF_E   (ROWS * XPITCH)          // 17152 : E_sh[e][half][tid] = 50*256
#define OFF_EW  (OFF_E + NE * ROWS)      // 29952 : E_W 66*50
#define OFF_AB  (OFF_EW + NIN * NE)      // 33252 : A_b 66*20
#define OFF_W   (OFF_AB + NIN * NA)      // 34572 : A_W double buffer 2*1000 (16B aligned)
#define SMEM_FLOATS (OFF_W + 2000)       // 36572 floats = 146288 B

// ---------------------------------------------------------------------------
// Packed f32x2 helpers (sm_100a+): 2 fp32 lanes per FMA instruction.
// ---------------------------------------------------------------------------
__device__ __forceinline__ unsigned long long dup2(float v) {
    unsigned long long r;
    asm("mov.b64 %0, {%1, %1};" : "=l"(r) : "f"(v));
    return r;
}
__device__ __forceinline__ void fma2(unsigned long long& d,
                                     unsigned long long a,
                                     unsigned long long b) {
    asm("fma.rn.f32x2 %0, %1, %2, %0;" : "+l"(d) : "l"(a), "l"(b));
}
__device__ __forceinline__ float lo32(unsigned long long v) {
    return __uint_as_float((unsigned)v);
}
__device__ __forceinline__ float hi32(unsigned long long v) {
    return __uint_as_float((unsigned)(v >> 32));
}

__device__ __forceinline__ void cp16(void* smem, const void* g) {
    uint32_t s = (uint32_t)__cvta_generic_to_shared(smem);
    asm volatile("cp.async.ca.shared.global [%0], [%1], 16;" :: "r"(s), "l"(g));
}

// ---------------------------------------------------------------------------
// One block = 256 rows, 128 threads, 2 rows/thread (register blocking on the
// batch dim amortizes the weight LDS across 2x the FMA work -> L1 pipe drops
// from ~91% to ~55%, FMA pipe becomes binding).
//  Phase 1: E[50] = tanh(x_row @ E_W + E_b) per row -> E_sh (conflict-free)
//  Phase 2: per feature i: s[20] = E @ A_W[i] + A_b[i]; A = 1/sum exp(s-s1);
//           x_sh[row][i] *= A; A_W double-buffered via cp.async.
// ---------------------------------------------------------------------------
__global__ void __launch_bounds__(THREADS, 1)
attn_kernel(const float* __restrict__ x,  const float* __restrict__ EW,
            const float* __restrict__ Eb, const float* __restrict__ AW,
            const float* __restrict__ Ab, float* __restrict__ out)
{
    extern __shared__ float sh[];
    float* x_sh  = sh + OFF_X;
    float* e_sh  = sh + OFF_E;
    float* ew_sh = sh + OFF_EW;
    float* ab_sh = sh + OFF_AB;
    float* w_sh  = sh + OFF_W;

    const int tid = threadIdx.x;
    const long long base = (long long)blockIdx.x * ROWS;

    // Stage A_W[0], A_W[1] early (overlaps the staging loops below).
    for (int j = tid; j < 250; j += THREADS) cp16(w_sh + j * 4, AW + j * 4);
    asm volatile("cp.async.commit_group;");
    for (int j = tid; j < 250; j += THREADS) cp16(w_sh + 1000 + j * 4, AW + 1000 + j * 4);
    asm volatile("cp.async.commit_group;");

    // Coalesced tile loads.
    const float* xg = x + base * NIN;
    for (int idx = tid; idx < ROWS * NIN; idx += THREADS)
        x_sh[(idx / NIN) * XPITCH + (idx % NIN)] = xg[idx];
    for (int idx = tid; idx < NIN * NE; idx += THREADS) ew_sh[idx] = EW[idx];
    for (int idx = tid; idx < NIN * NA; idx += THREADS) ab_sh[idx] = Ab[idx];
    __syncthreads();

    // ------------- Phase 1: E = tanh(x @ E_W + E_b), 2 rows/thread ---------
#pragma unroll 1
    for (int half = 0; half < 2; ++half) {
        const float* xr = x_sh + (tid + half * THREADS) * XPITCH;
        unsigned long long eacc[NE / 2];
#pragma unroll
        for (int p = 0; p < NE / 2; ++p) eacc[p] = 0ULL;

#pragma unroll 2
        for (int i = 0; i < NIN; ++i) {
            unsigned long long x2 = dup2(xr[i]);
            const unsigned long long* w =
                reinterpret_cast<const unsigned long long*>(ew_sh + i * NE);
#pragma unroll
            for (int p = 0; p < NE / 2; ++p) fma2(eacc[p], x2, w[p]);
        }
#pragma unroll
        for (int p = 0; p < NE / 2; ++p) {
            float e0 = tanhf(lo32(eacc[p]) + __ldg(Eb + 2 * p));
            float e1 = tanhf(hi32(eacc[p]) + __ldg(Eb + 2 * p + 1));
            e_sh[(2 * p) * ROWS + half * THREADS + tid]     = e0;
            e_sh[(2 * p + 1) * ROWS + half * THREADS + tid] = e1;
        }
    }

    // ------------- Phase 2: per-feature attention, 2 rows/thread -----------
    float* xr0 = x_sh + tid * XPITCH;
    float* xr1 = x_sh + (tid + THREADS) * XPITCH;

#pragma unroll 1
    for (int i = 0; i < NIN; ++i) {
        asm volatile("cp.async.wait_group 1;");   // A_W[i] resident
        __syncthreads();

        const float* W = w_sh + (i & 1) * 1000;
        const ulonglong2* ab =
            reinterpret_cast<const ulonglong2*>(ab_sh + i * NA);  // 16B aligned

        unsigned long long acc0[NA / 2], acc1[NA / 2];
#pragma unroll
        for (int q = 0; q < 5; ++q) {
            ulonglong2 b = ab[q];                  // broadcast LDS.128
            acc0[2 * q] = b.x;  acc0[2 * q + 1] = b.y;
            acc1[2 * q] = b.x;  acc1[2 * q + 1] = b.y;
        }

#pragma unroll
        for (int e = 0; e < NE; ++e) {
            unsigned long long ea = dup2(e_sh[e * ROWS + tid]);            // row t
            unsigned long long eb = dup2(e_sh[e * ROWS + THREADS + tid]);  // row t+128
            const ulonglong2* we =
                reinterpret_cast<const ulonglong2*>(W + e * NA);  // 16B aligned
#pragma unroll
            for (int q = 0; q < 5; ++q) {
                ulonglong2 wv = we[q];             // broadcast LDS.128 (shared by 2 rows)
                fma2(acc0[2 * q],     ea, wv.x);
                fma2(acc0[2 * q + 1], ea, wv.y);
                fma2(acc1[2 * q],     eb, wv.x);
                fma2(acc1[2 * q + 1], eb, wv.y);
            }
        }

        // Softmax over 20 classes; keep class 1. Max-free: denom >= exp(0)=1.
        {
            float s1 = hi32(acc0[0]);
            float d = 0.0f;
#pragma unroll
            for (int p = 0; p < NA / 2; ++p) {
                d += __expf(lo32(acc0[p]) - s1);
                d += __expf(hi32(acc0[p]) - s1);
            }
            xr0[i] *= __fdividef(1.0f, d);
        }
        {
            float s1 = hi32(acc1[0]);
            float d = 0.0f;
#pragma unroll
            for (int p = 0; p < NA / 2; ++p) {
                d += __expf(lo32(acc1[p]) - s1);
                d += __expf(hi32(acc1[p]) - s1);
            }
            xr1[i] *= __fdividef(1.0f, d);
        }

        __syncthreads();                      // all readers done with buf (i&1)
        if (i + 2 < NIN) {                    // prefetch A_W[i+2] into freed buf
            for (int j = tid; j < 250; j += THREADS)
                cp16(w_sh + (i & 1) * 1000 + j * 4, AW + (i + 2) * 1000 + j * 4);
        }
        asm volatile("cp.async.commit_group;");  // commit (possibly empty) group
    }

    // Coalesced writeback.
    __syncthreads();
    float* og = out + base * NIN;
    for (int idx = tid; idx < ROWS * NIN; idx += THREADS)
        og[idx] = x_sh[(idx / NIN) * XPITCH + (idx % NIN)];
}

extern "C" void kernel_launch(void* const* d_in, const int* in_sizes, int n_in,
                              void* d_out, int out_size) {
    const float* x  = (const float*)d_in[0];
    const float* EW = (const float*)d_in[1];
    const float* Eb = (const float*)d_in[2];
    const float* AW = (const float*)d_in[3];
    const float* Ab = (const float*)d_in[4];
    float* out = (float*)d_out;

    const size_t smem = SMEM_FLOATS * sizeof(float);
    cudaFuncSetAttribute(attn_kernel,
                         cudaFuncAttributeMaxDynamicSharedMemorySize, (int)smem);
    attn_kernel<<<B_TOTAL / ROWS, THREADS, smem>>>(x, EW, Eb, AW, Ab, out);
}

// round 5
// speedup vs baseline: 1.3409x; 1.2134x over previous
#include <cuda_runtime.h>
#include <cstdint>

// Problem constants (fixed shapes from reference setup_inputs)
#define B_TOTAL 262144
#define NIN 66      // input features
#define NE  50      // E_NODE
#define NA  20      // A_NODE
#define THREADS 128
#define ROWS 256    // rows per block; 2 rows per thread (tid and tid+128)
#define XPITCH 67   // x tile pitch: lane stride 67 -> conflict-free per-row access
#define EWPITCH 52  // E_W row pitch (16B aligned rows)

// Shared layout (float offsets)
#define OFF_X   0
#define OFF_EW  (ROWS * XPITCH)            // 17152 : E_W 66 x 52
#define OFF_AB  (OFF_EW + NIN * EWPITCH)   // 20584 : A_b 66 x 20
#define OFF_W   (OFF_AB + NIN * NA)        // 21904 : A_W double buffer 2 x 1000 (16B aligned)
#define SMEM_FLOATS (OFF_W + 2000)         // 23904 floats = 95616 B -> 2 blocks/SM

// ---------------------------------------------------------------------------
// Packed f32x2 helpers (sm_100a+): 2 fp32 lanes per FMA instruction.
// ---------------------------------------------------------------------------
__device__ __forceinline__ unsigned long long dup2(float v) {
    unsigned long long r;
    asm("mov.b64 %0, {%1, %1};" : "=l"(r) : "f"(v));
    return r;
}
__device__ __forceinline__ void fma2(unsigned long long& d,
                                     unsigned long long a,
                                     unsigned long long b) {
    asm("fma.rn.f32x2 %0, %1, %2, %0;" : "+l"(d) : "l"(a), "l"(b));
}
__device__ __forceinline__ float lo32(unsigned long long v) {
    return __uint_as_float((unsigned)v);
}
__device__ __forceinline__ float hi32(unsigned long long v) {
    return __uint_as_float((unsigned)(v >> 32));
}

__device__ __forceinline__ void cp16(void* smem, const void* g) {
    uint32_t s = (uint32_t)__cvta_generic_to_shared(smem);
    asm volatile("cp.async.ca.shared.global [%0], [%1], 16;" :: "r"(s), "l"(g));
}

// ---------------------------------------------------------------------------
// 128 threads/block, 2 rows/thread, E kept entirely in registers (100 fp32)
// -> no E shared array -> 95.6KB smem -> 2 blocks/SM -> 2 warps/SMSP.
// ---------------------------------------------------------------------------
__global__ void __launch_bounds__(THREADS, 2)
attn_kernel(const float* __restrict__ x,  const float* __restrict__ EW,
            const float* __restrict__ Eb, const float* __restrict__ AW,
            const float* __restrict__ Ab, float* __restrict__ out)
{
    extern __shared__ float sh[];
    float* x_sh  = sh + OFF_X;
    float* ew_sh = sh + OFF_EW;
    float* ab_sh = sh + OFF_AB;
    float* w_sh  = sh + OFF_W;

    const int tid = threadIdx.x;
    const long long base = (long long)blockIdx.x * ROWS;

    // Stage A_W[0], A_W[1] early (overlaps the staging loops below).
    for (int j = tid; j < 250; j += THREADS) cp16(w_sh + j * 4, AW + j * 4);
    asm volatile("cp.async.commit_group;");
    for (int j = tid; j < 250; j += THREADS) cp16(w_sh + 1000 + j * 4, AW + 1000 + j * 4);
    asm volatile("cp.async.commit_group;");

    // Coalesced tile loads.
    const float* xg = x + base * NIN;
    for (int idx = tid; idx < ROWS * NIN; idx += THREADS)
        x_sh[(idx / NIN) * XPITCH + (idx % NIN)] = xg[idx];
    for (int idx = tid; idx < NIN * NE; idx += THREADS)
        ew_sh[(idx / NE) * EWPITCH + (idx % NE)] = EW[idx];
    for (int idx = tid; idx < NIN * NA; idx += THREADS) ab_sh[idx] = Ab[idx];
    __syncthreads();

    // ------------- Phase 1: E = tanh(x @ E_W + E_b), both rows interleaved --
    const float* xr0 = x_sh + tid * XPITCH;
    const float* xr1 = x_sh + (tid + THREADS) * XPITCH;

    unsigned long long eacc0[NE / 2], eacc1[NE / 2];
#pragma unroll
    for (int p = 0; p < NE / 2; ++p) { eacc0[p] = 0ULL; eacc1[p] = 0ULL; }

#pragma unroll 2
    for (int i = 0; i < NIN; ++i) {
        unsigned long long xa = dup2(xr0[i]);
        unsigned long long xb = dup2(xr1[i]);
        const float* wrow = ew_sh + i * EWPITCH;  // 16B aligned
        const ulonglong2* w2 = reinterpret_cast<const ulonglong2*>(wrow);
#pragma unroll
        for (int q = 0; q < 12; ++q) {            // 48 floats via LDS.128
            ulonglong2 wv = w2[q];
            fma2(eacc0[2 * q],     xa, wv.x);
            fma2(eacc0[2 * q + 1], xa, wv.y);
            fma2(eacc1[2 * q],     xb, wv.x);
            fma2(eacc1[2 * q + 1], xb, wv.y);
        }
        unsigned long long wt =                    // last 2 floats (LDS.64)
            reinterpret_cast<const unsigned long long*>(wrow)[24];
        fma2(eacc0[24], xa, wt);
        fma2(eacc1[24], xb, wt);
    }

    // E in registers: 2 rows x 50 fp32.
    float E0[NE], E1[NE];
#pragma unroll
    for (int p = 0; p < NE / 2; ++p) {
        float b0 = __ldg(Eb + 2 * p), b1 = __ldg(Eb + 2 * p + 1);
        E0[2 * p]     = tanhf(lo32(eacc0[p]) + b0);
        E0[2 * p + 1] = tanhf(hi32(eacc0[p]) + b1);
        E1[2 * p]     = tanhf(lo32(eacc1[p]) + b0);
        E1[2 * p + 1] = tanhf(hi32(eacc1[p]) + b1);
    }

    // ------------- Phase 2: per-feature attention, 2 rows/thread -----------
    float* xw0 = x_sh + tid * XPITCH;
    float* xw1 = x_sh + (tid + THREADS) * XPITCH;

#pragma unroll 1
    for (int i = 0; i < NIN; ++i) {
        asm volatile("cp.async.wait_group 1;");   // A_W[i] resident
        __syncthreads();

        const float* W = w_sh + (i & 1) * 1000;
        const ulonglong2* ab =
            reinterpret_cast<const ulonglong2*>(ab_sh + i * NA);  // 16B aligned

        unsigned long long acc0[NA / 2], acc1[NA / 2];
#pragma unroll
        for (int q = 0; q < 5; ++q) {
            ulonglong2 b = ab[q];                  // broadcast LDS.128
            acc0[2 * q] = b.x;  acc0[2 * q + 1] = b.y;
            acc1[2 * q] = b.x;  acc1[2 * q + 1] = b.y;
        }

#pragma unroll
        for (int e = 0; e < NE; ++e) {
            unsigned long long ea = dup2(E0[e]);   // 2 MOV, ALU pipe
            unsigned long long eb = dup2(E1[e]);
            const ulonglong2* we =
                reinterpret_cast<const ulonglong2*>(W + e * NA);  // 16B aligned
#pragma unroll
            for (int q = 0; q < 5; ++q) {
                ulonglong2 wv = we[q];             // broadcast LDS.128, shared by 2 rows
                fma2(acc0[2 * q],     ea, wv.x);
                fma2(acc0[2 * q + 1], ea, wv.y);
                fma2(acc1[2 * q],     eb, wv.x);
                fma2(acc1[2 * q + 1], eb, wv.y);
            }
        }

        // Softmax over 20 classes; keep class 1. Max-free: denom >= exp(0)=1.
        {
            float s1 = hi32(acc0[0]);
            float d = 0.0f;
#pragma unroll
            for (int p = 0; p < NA / 2; ++p) {
                d += __expf(lo32(acc0[p]) - s1);
                d += __expf(hi32(acc0[p]) - s1);
            }
            xw0[i] *= __fdividef(1.0f, d);
        }
        {
            float s1 = hi32(acc1[0]);
            float d = 0.0f;
#pragma unroll
            for (int p = 0; p < NA / 2; ++p) {
                d += __expf(lo32(acc1[p]) - s1);
                d += __expf(hi32(acc1[p]) - s1);
            }
            xw1[i] *= __fdividef(1.0f, d);
        }

        __syncthreads();                      // all readers done with buf (i&1)
        if (i + 2 < NIN) {                    // prefetch A_W[i+2] into freed buf
            for (int j = tid; j < 250; j += THREADS)
                cp16(w_sh + (i & 1) * 1000 + j * 4, AW + (i + 2) * 1000 + j * 4);
        }
        asm volatile("cp.async.commit_group;");  // commit (possibly empty) group
    }

    // Coalesced writeback.
    __syncthreads();
    float* og = out + base * NIN;
    for (int idx = tid; idx < ROWS * NIN; idx += THREADS)
        og[idx] = x_sh[(idx / NIN) * XPITCH + (idx % NIN)];
}

extern "C" void kernel_launch(void* const* d_in, const int* in_sizes, int n_in,
                              void* d_out, int out_size) {
    const float* x  = (const float*)d_in[0];
    const float* EW = (const float*)d_in[1];
    const float* Eb = (const float*)d_in[2];
    const float* AW = (const float*)d_in[3];
    const float* Ab = (const float*)d_in[4];
    float* out = (float*)d_out;

    const size_t smem = SMEM_FLOATS * sizeof(float);
    cudaFuncSetAttribute(attn_kernel,
                         cudaFuncAttributeMaxDynamicSharedMemorySize, (int)smem);
    attn_kernel<<<B_TOTAL / ROWS, THREADS, smem>>>(x, EW, Eb, AW, Ab, out);
}

// round 7
// speedup vs baseline: 1.9262x; 1.4365x over previous
#include <cuda_runtime.h>
#include <cuda_bf16.h>
#include <cstdint>
#include <cstring>

// ---------------------------------------------------------------------------
// Problem constants
// ---------------------------------------------------------------------------
#define B_TOTAL 262144
#define NIN 66
#define NE  50
#define NA  20
#define MTILE 128            // rows per CTA
#define THREADS 128          // 4 warps, 32 rows each (2 m16 slabs)
#define NITER 33             // 33 x 40 cols = 1320 = 66*20
#define NPI 40               // cols per iteration (2 features)
#define NCHUNKS 5            // five m16n8 chunks per iteration
#define KSTEPS 10            // K = 160 bf16 (152 real + pad)
#define XPITCH 67
#define EWPITCH 52
#define EPITCH 164           // e_img pitch in bf16 (328 B rows)
#define SPITCH 42            // s_tile pitch in f32 (168 B rows)

// smem byte offsets
#define BITER 12800          // 5*10*64 u32 = bytes per iteration's B fragments
#define OFF_B0 0
#define OFF_B1 12800
#define OFF_X  25600         // x tile: 128*67*4 = 34304
#define OFF_U  59904         // union: ew_sh(13728) / e_img(41984) / s_tile(21504)
#define SMEM_BYTES (OFF_U + 41984)   // 101888 -> 2 CTAs/SM

// ---------------------------------------------------------------------------
// Pre-packed B fragments (global): [iter][chunk][kstep][lane][2] u32,
// exact mma.sync m16n8k16 B-fragment register order.
// ---------------------------------------------------------------------------
__device__ __align__(16) uint32_t b_img[NITER * NCHUNKS * KSTEPS * 64];

// ---------------------------------------------------------------------------
// Helpers
// ---------------------------------------------------------------------------
__device__ __forceinline__ uint32_t pack_bf16(float lo, float hi) {
    __nv_bfloat162 v = __floats2bfloat162_rn(lo, hi);
    uint32_t u; memcpy(&u, &v, 4); return u;
}
__device__ __forceinline__ void cp16(void* s, const void* g) {
    uint32_t sa;
    asm("{ .reg .u64 t; cvta.to.shared.u64 t, %1; cvt.u32.u64 %0, t; }"
        : "=r"(sa) : "l"(s));
    asm volatile("cp.async.ca.shared.global [%0], [%1], 16;" :: "r"(sa), "l"(g));
}
#define CP_COMMIT() asm volatile("cp.async.commit_group;")
#define CP_WAIT1()  asm volatile("cp.async.wait_group 1;")

__device__ __forceinline__ void mma16816(float* c, const uint32_t* a,
                                         uint32_t b0, uint32_t b1) {
    asm volatile(
        "mma.sync.aligned.m16n8k16.row.col.f32.bf16.bf16.f32 "
        "{%0,%1,%2,%3}, {%4,%5,%6,%7}, {%8,%9}, {%0,%1,%2,%3};"
        : "+f"(c[0]), "+f"(c[1]), "+f"(c[2]), "+f"(c[3])
        : "r"(a[0]), "r"(a[1]), "r"(a[2]), "r"(a[3]), "r"(b0), "r"(b1));
}

// packed f32x2 fma (phase 1)
__device__ __forceinline__ unsigned long long dup2(float v) {
    unsigned long long r; asm("mov.b64 %0, {%1, %1};" : "=l"(r) : "f"(v)); return r;
}
__device__ __forceinline__ void fma2(unsigned long long& d, unsigned long long a,
                                     unsigned long long b) {
    asm("fma.rn.f32x2 %0, %1, %2, %0;" : "+l"(d) : "l"(a), "l"(b));
}
__device__ __forceinline__ float lo32(unsigned long long v) { return __uint_as_float((unsigned)v); }
__device__ __forceinline__ float hi32(unsigned long long v) { return __uint_as_float((unsigned)(v >> 32)); }

// ---------------------------------------------------------------------------
// Prep kernel: build B fragments. Logical W[k][n], n = i*20 + a:
//   k<50   : Wh[k]       (pairs Eh)        k in [100,150): Wl residual (pairs Eh)
//   k<100  : Wh[k-50]    (pairs El)        k==150: bias hi; k==151: bias lo; else 0
// Fragment order: reg r of lane l in (iter,chunk,kstep): col n = base + l/4,
// rows k0 = ks*16 + (l%4)*2 + r*8, values {k0, k0+1} packed lo/hi.
// ---------------------------------------------------------------------------
__global__ void prep_kernel(const float* __restrict__ AW, const float* __restrict__ Ab) {
    int idx = blockIdx.x * 256 + threadIdx.x;
    if (idx >= NITER * NCHUNKS * KSTEPS * 64) return;
    int reg  = idx & 1;
    int lane = (idx >> 1) & 31;
    int rest = idx >> 6;
    int ks = rest % KSTEPS;
    int ch = (rest / KSTEPS) % NCHUNKS;
    int it = rest / (KSTEPS * NCHUNKS);

    int n = it * NPI + ch * 8 + (lane >> 2);
    int i = n / NA, a = n % NA;
    int k0 = ks * 16 + (lane & 3) * 2 + reg * 8;

    float v[2];
#pragma unroll
    for (int t = 0; t < 2; ++t) {
        int k = k0 + t;
        float val = 0.0f;
        if (k < 100) {
            val = AW[i * 1000 + (k % 50) * 20 + a];                 // Wh
        } else if (k < 150) {
            float w = AW[i * 1000 + (k - 100) * 20 + a];            // Wl residual
            val = w - __bfloat162float(__float2bfloat16(w));
        } else if (k == 150) {
            val = Ab[i * 20 + a];                                   // bias hi
        } else if (k == 151) {
            float b = Ab[i * 20 + a];                               // bias lo
            val = b - __bfloat162float(__float2bfloat16(b));
        }
        v[t] = val;
    }
    b_img[idx] = pack_bf16(v[0], v[1]);
}

// ---------------------------------------------------------------------------
// Main kernel
// ---------------------------------------------------------------------------
__global__ void __launch_bounds__(THREADS, 2)
attn_mma(const float* __restrict__ x,  const float* __restrict__ EW,
         const float* __restrict__ Eb, float* __restrict__ out)
{
    extern __shared__ __align__(16) unsigned char smem[];
    float* x_sh  = reinterpret_cast<float*>(smem + OFF_X);
    float* ew_sh = reinterpret_cast<float*>(smem + OFF_U);     // phase-1 only
    unsigned char* e_img = smem + OFF_U;                       // after phase 1
    float* s_tile = reinterpret_cast<float*>(smem + OFF_U);    // main loop

    const int tid = threadIdx.x;
    const int wid = tid >> 5;
    const int lid = tid & 31;
    const int g   = lid >> 2;     // fragment group row
    const int tig = lid & 3;      // thread-in-group
    const long long base = (long long)blockIdx.x * MTILE;

    // Prologue: prefetch B fragments for iters 0 and 1.
    const unsigned char* bg = reinterpret_cast<const unsigned char*>(b_img);
    for (int j = tid; j < BITER / 16; j += THREADS)
        cp16(smem + OFF_B0 + j * 16, bg + j * 16);
    CP_COMMIT();
    for (int j = tid; j < BITER / 16; j += THREADS)
        cp16(smem + OFF_B1 + j * 16, bg + BITER + j * 16);
    CP_COMMIT();

    // Stage x tile + E_W.
    const float* xg = x + base * NIN;
    for (int idx = tid; idx < MTILE * NIN; idx += THREADS)
        x_sh[(idx / NIN) * XPITCH + (idx % NIN)] = xg[idx];
    for (int idx = tid; idx < NIN * NE; idx += THREADS)
        ew_sh[(idx / NE) * EWPITCH + (idx % NE)] = EW[idx];
    __syncthreads();

    // ---------------- Phase 1: E = tanh(x @ E_W + E_b), 1 row/thread --------
    const float* xr = x_sh + tid * XPITCH;
    unsigned long long eacc[NE / 2];
#pragma unroll
    for (int p = 0; p < NE / 2; ++p) eacc[p] = 0ULL;
#pragma unroll 2
    for (int i = 0; i < NIN; ++i) {
        unsigned long long xv = dup2(xr[i]);
        const float* wrow = ew_sh + i * EWPITCH;
        const ulonglong2* w2 = reinterpret_cast<const ulonglong2*>(wrow);
#pragma unroll
        for (int q = 0; q < 12; ++q) {
            ulonglong2 wv = w2[q];
            fma2(eacc[2 * q], xv, wv.x);
            fma2(eacc[2 * q + 1], xv, wv.y);
        }
        unsigned long long wt = reinterpret_cast<const unsigned long long*>(wrow)[24];
        fma2(eacc[24], xv, wt);
    }
    float E[NE];
#pragma unroll
    for (int p = 0; p < NE / 2; ++p) {
        E[2 * p]     = tanhf(lo32(eacc[p]) + __ldg(Eb + 2 * p));
        E[2 * p + 1] = tanhf(hi32(eacc[p]) + __ldg(Eb + 2 * p + 1));
    }
    __syncthreads();   // everyone done reading ew_sh; e_img may overwrite it

    // Build augmented E image (bf16): cols 0-49 Eh | 50-99 El | 100-149 Eh |
    // 150-151 = 1.0 (bias lanes) | 152-159 zero.   Row = tid, pitch 328 B.
    {
        uint32_t* er = reinterpret_cast<uint32_t*>(e_img + tid * (EPITCH * 2));
#pragma unroll
        for (int p = 0; p < 25; ++p) {
            float e0 = E[2 * p], e1 = E[2 * p + 1];
            __nv_bfloat162 h2 = __floats2bfloat162_rn(e0, e1);
            uint32_t hv; memcpy(&hv, &h2, 4);
            float r0 = e0 - __bfloat162float(__low2bfloat16(h2));
            float r1 = e1 - __bfloat162float(__high2bfloat16(h2));
            er[p]      = hv;                         // Eh
            er[25 + p] = pack_bf16(r0, r1);          // El
            er[50 + p] = hv;                         // Eh (pairs Wl)
        }
        er[75] = pack_bf16(1.0f, 1.0f);              // bias lanes k=150,151
        er[76] = 0; er[77] = 0; er[78] = 0; er[79] = 0;
    }
    __syncthreads();

    // Load A fragments: 2 slabs x 10 ksteps x 4 regs = 80 regs, resident.
    uint32_t Af[2][KSTEPS][4];
#pragma unroll
    for (int s = 0; s < 2; ++s) {
        int RB = wid * 32 + s * 16;
        const unsigned char* eb = e_img;
#pragma unroll
        for (int ks = 0; ks < KSTEPS; ++ks) {
            int kc = (ks * 16 + tig * 2) * 2;        // byte offset of k pair
            Af[s][ks][0] = *reinterpret_cast<const uint32_t*>(eb + (RB + g) * 328 + kc);
            Af[s][ks][1] = *reinterpret_cast<const uint32_t*>(eb + (RB + g + 8) * 328 + kc);
            Af[s][ks][2] = *reinterpret_cast<const uint32_t*>(eb + (RB + g) * 328 + kc + 16);
            Af[s][ks][3] = *reinterpret_cast<const uint32_t*>(eb + (RB + g + 8) * 328 + kc + 16);
        }
    }
    __syncthreads();   // A frags in regs everywhere; e_img region free for s_tile

    // ---------------- Main loop: 33 iterations of 40 columns ----------------
#pragma unroll 1
    for (int c = 0; c < NITER; ++c) {
        CP_WAIT1();          // this iter's B fragments resident
        __syncthreads();

        const uint32_t* bbuf =
            reinterpret_cast<const uint32_t*>(smem + ((c & 1) ? OFF_B1 : OFF_B0));

        float C[2][NCHUNKS][4];
#pragma unroll
        for (int s = 0; s < 2; ++s)
#pragma unroll
            for (int ch = 0; ch < NCHUNKS; ++ch)
#pragma unroll
                for (int q = 0; q < 4; ++q) C[s][ch][q] = 0.0f;

#pragma unroll
        for (int ch = 0; ch < NCHUNKS; ++ch) {
#pragma unroll
            for (int ks = 0; ks < KSTEPS; ++ks) {
                uint2 bv = *reinterpret_cast<const uint2*>(
                    bbuf + (ch * KSTEPS + ks) * 64 + lid * 2);
                mma16816(C[0][ch], Af[0][ks], bv.x, bv.y);
                mma16816(C[1][ch], Af[1][ks], bv.x, bv.y);
            }
        }

        // Stage scores to s_tile (128 x 40, pitch 42 f32).
#pragma unroll
        for (int s = 0; s < 2; ++s) {
            int r0 = wid * 32 + s * 16 + g;
#pragma unroll
            for (int ch = 0; ch < NCHUNKS; ++ch) {
                *reinterpret_cast<float2*>(s_tile + r0 * SPITCH + ch * 8 + tig * 2) =
                    make_float2(C[s][ch][0], C[s][ch][1]);
                *reinterpret_cast<float2*>(s_tile + (r0 + 8) * SPITCH + ch * 8 + tig * 2) =
                    make_float2(C[s][ch][2], C[s][ch][3]);
            }
        }
        __syncthreads();     // compute + STS done; B buffer (c&1) free

        if (c + 2 < NITER) { // prefetch iter c+2 into freed buffer
            const unsigned char* src = bg + (size_t)(c + 2) * BITER;
            for (int j = tid; j < BITER / 16; j += THREADS)
                cp16(smem + ((c & 1) ? OFF_B1 : OFF_B0) + j * 16, src + j * 16);
        }
        CP_COMMIT();         // always commit (possibly empty) to keep count

        // Softmax: thread = row tid, 2 features. denom includes a==1 (exp(0)=1).
#pragma unroll
        for (int f = 0; f < 2; ++f) {
            const float* sp = s_tile + tid * SPITCH + f * 20;
            float s1 = sp[1];
            float denom = 0.0f;
#pragma unroll
            for (int j = 0; j < 10; ++j) {
                float2 v = *reinterpret_cast<const float2*>(sp + 2 * j);
                denom += __expf(v.x - s1) + __expf(v.y - s1);
            }
            int i = c * 2 + f;
            x_sh[tid * XPITCH + i] *= __fdividef(1.0f, denom);
        }
        // next iter's sync #1 orders softmax reads before s_tile overwrite
    }
    __syncthreads();

    // Coalesced writeback.
    float* og = out + base * NIN;
    for (int idx = tid; idx < MTILE * NIN; idx += THREADS)
        og[idx] = x_sh[(idx / NIN) * XPITCH + (idx % NIN)];
}

// ---------------------------------------------------------------------------
extern "C" void kernel_launch(void* const* d_in, const int* in_sizes, int n_in,
                              void* d_out, int out_size) {
    const float* x  = (const float*)d_in[0];
    const float* EW = (const float*)d_in[1];
    const float* Eb = (const float*)d_in[2];
    const float* AW = (const float*)d_in[3];
    const float* Ab = (const float*)d_in[4];
    float* out = (float*)d_out;

    int prep_elems = NITER * NCHUNKS * KSTEPS * 64;
    prep_kernel<<<(prep_elems + 255) / 256, 256>>>(AW, Ab);

    cudaFuncSetAttribute(attn_mma,
                         cudaFuncAttributeMaxDynamicSharedMemorySize, SMEM_BYTES);
    attn_mma<<<B_TOTAL / MTILE, THREADS, SMEM_BYTES>>>(x, EW, Eb, out);
}

// round 8
// speedup vs baseline: 2.5372x; 1.3172x over previous
#include <cuda_runtime.h>
#include <cuda_bf16.h>
#include <cstdint>
#include <cstring>

// ---------------------------------------------------------------------------
// Problem constants
// ---------------------------------------------------------------------------
#define B_TOTAL 262144
#define NIN 66
#define NE  50
#define NA  20
#define MTILE 128            // rows per CTA
#define THREADS 128          // 4 warps, 32 rows each (2 m16 slabs)
#define NITER 33             // 33 x 40 cols = 1320 = 66*20
#define NPI 40               // cols per iteration (2 features)
#define NCHUNKS 5            // five m16n8 chunks per iteration
#define KSTEPS 10            // K = 160 bf16 (152 real + pad)
#define XPITCH 67
#define EWPITCH 52

// smem byte offsets
#define BITER 12800          // bytes per iteration's B fragments
#define OFF_B0 0
#define OFF_B1 12800
#define OFF_X  25600         // x tile: 128*67*4 = 34304
#define OFF_EW 59904         // E_W: 66*52*4 = 13728 (phase-1 only)
#define SMEM_BYTES 73632     // -> 3 CTAs/SM

// ---------------------------------------------------------------------------
// Pre-packed B fragments (global): [iter][chunk][kstep][lane][2] u32,
// exact mma.sync m16n8k16 B-fragment register order.  (unchanged from R7)
// ---------------------------------------------------------------------------
__device__ __align__(16) uint32_t b_img[NITER * NCHUNKS * KSTEPS * 64];

// ---------------------------------------------------------------------------
// Helpers
// ---------------------------------------------------------------------------
__device__ __forceinline__ uint32_t pack_bf16(float lo, float hi) {
    __nv_bfloat162 v = __floats2bfloat162_rn(lo, hi);
    uint32_t u; memcpy(&u, &v, 4); return u;
}
__device__ __forceinline__ void cp16(void* s, const void* g) {
    uint32_t sa;
    asm("{ .reg .u64 t; cvta.to.shared.u64 t, %1; cvt.u32.u64 %0, t; }"
        : "=r"(sa) : "l"(s));
    asm volatile("cp.async.ca.shared.global [%0], [%1], 16;" :: "r"(sa), "l"(g));
}
#define CP_COMMIT() asm volatile("cp.async.commit_group;")
#define CP_WAIT1()  asm volatile("cp.async.wait_group 1;")

__device__ __forceinline__ void mma16816(float* c, const uint32_t* a,
                                         uint32_t b0, uint32_t b1) {
    asm volatile(
        "mma.sync.aligned.m16n8k16.row.col.f32.bf16.bf16.f32 "
        "{%0,%1,%2,%3}, {%4,%5,%6,%7}, {%8,%9}, {%0,%1,%2,%3};"
        : "+f"(c[0]), "+f"(c[1]), "+f"(c[2]), "+f"(c[3])
        : "r"(a[0]), "r"(a[1]), "r"(a[2]), "r"(a[3]), "r"(b0), "r"(b1));
}

// packed f32x2 fma (phase 1)
__device__ __forceinline__ unsigned long long dup2(float v) {
    unsigned long long r; asm("mov.b64 %0, {%1, %1};" : "=l"(r) : "f"(v)); return r;
}
__device__ __forceinline__ void fma2(unsigned long long& d, unsigned long long a,
                                     unsigned long long b) {
    asm("fma.rn.f32x2 %0, %1, %2, %0;" : "+l"(d) : "l"(a), "l"(b));
}
__device__ __forceinline__ float lo32(unsigned long long v) { return __uint_as_float((unsigned)v); }
__device__ __forceinline__ float hi32(unsigned long long v) { return __uint_as_float((unsigned)(v >> 32)); }

// Augmented-E column-pair select (compile-time j): cols 2j,2j+1 of
// [Eh(0..49) | El(50..99) | Eh(100..149) | 1,1 (150..151) | 0 (152..159)]
__device__ __forceinline__ uint32_t colsel(const uint32_t* Ehp, const uint32_t* Elp,
                                           uint32_t one2, int j) {
    if (j < 25) return Ehp[j];
    if (j < 50) return Elp[j - 25];
    if (j < 75) return Ehp[j - 50];
    if (j == 75) return one2;
    return 0u;
}

// ---------------------------------------------------------------------------
// Prep kernel (unchanged from R7 — verified): B fragments for logical W[k][n],
// n = i*20 + a:  k<50: Wh | k<100: Wh | k<150: Wl residual | 150/151: bias hi/lo
// ---------------------------------------------------------------------------
__global__ void prep_kernel(const float* __restrict__ AW, const float* __restrict__ Ab) {
    int idx = blockIdx.x * 256 + threadIdx.x;
    if (idx >= NITER * NCHUNKS * KSTEPS * 64) return;
    int reg  = idx & 1;
    int lane = (idx >> 1) & 31;
    int rest = idx >> 6;
    int ks = rest % KSTEPS;
    int ch = (rest / KSTEPS) % NCHUNKS;
    int it = rest / (KSTEPS * NCHUNKS);

    int n = it * NPI + ch * 8 + (lane >> 2);
    int i = n / NA, a = n % NA;
    int k0 = ks * 16 + (lane & 3) * 2 + reg * 8;

    float v[2];
#pragma unroll
    for (int t = 0; t < 2; ++t) {
        int k = k0 + t;
        float val = 0.0f;
        if (k < 100) {
            val = AW[i * 1000 + (k % 50) * 20 + a];
        } else if (k < 150) {
            float w = AW[i * 1000 + (k - 100) * 20 + a];
            val = w - __bfloat162float(__float2bfloat16(w));
        } else if (k == 150) {
            val = Ab[i * 20 + a];
        } else if (k == 151) {
            float b = Ab[i * 20 + a];
            val = b - __bfloat162float(__float2bfloat16(b));
        }
        v[t] = val;
    }
    b_img[idx] = pack_bf16(v[0], v[1]);
}

// ---------------------------------------------------------------------------
// Main kernel
// ---------------------------------------------------------------------------
__global__ void __launch_bounds__(THREADS, 3)
attn_mma(const float* __restrict__ x,  const float* __restrict__ EW,
         const float* __restrict__ Eb, float* __restrict__ out)
{
    extern __shared__ __align__(16) unsigned char smem[];
    float* x_sh  = reinterpret_cast<float*>(smem + OFF_X);
    float* ew_sh = reinterpret_cast<float*>(smem + OFF_EW);

    const int tid = threadIdx.x;
    const int wid = tid >> 5;
    const int lid = tid & 31;
    const int g   = lid >> 2;     // fragment group row
    const int tig = lid & 3;      // thread-in-group
    const long long base = (long long)blockIdx.x * MTILE;

    // Prologue: prefetch B fragments for iters 0 and 1.
    const unsigned char* bg = reinterpret_cast<const unsigned char*>(b_img);
    for (int j = tid; j < BITER / 16; j += THREADS)
        cp16(smem + OFF_B0 + j * 16, bg + j * 16);
    CP_COMMIT();
    for (int j = tid; j < BITER / 16; j += THREADS)
        cp16(smem + OFF_B1 + j * 16, bg + BITER + j * 16);
    CP_COMMIT();

    // Stage x tile + E_W.
    const float* xg = x + base * NIN;
    for (int idx = tid; idx < MTILE * NIN; idx += THREADS)
        x_sh[(idx / NIN) * XPITCH + (idx % NIN)] = xg[idx];
    for (int idx = tid; idx < NIN * NE; idx += THREADS)
        ew_sh[(idx / NE) * EWPITCH + (idx % NE)] = EW[idx];
    __syncthreads();

    // ---------------- Phase 1: E = tanh(x @ E_W + E_b), 1 row/thread --------
    const float* xr = x_sh + tid * XPITCH;
    unsigned long long eacc[NE / 2];
#pragma unroll
    for (int p = 0; p < NE / 2; ++p) eacc[p] = 0ULL;
#pragma unroll 2
    for (int i = 0; i < NIN; ++i) {
        unsigned long long xv = dup2(xr[i]);
        const float* wrow = ew_sh + i * EWPITCH;
        const ulonglong2* w2 = reinterpret_cast<const ulonglong2*>(wrow);
#pragma unroll
        for (int q = 0; q < 12; ++q) {
            ulonglong2 wv = w2[q];
            fma2(eacc[2 * q], xv, wv.x);
            fma2(eacc[2 * q + 1], xv, wv.y);
        }
        unsigned long long wt = reinterpret_cast<const unsigned long long*>(wrow)[24];
        fma2(eacc[24], xv, wt);
    }

    // Packed bf16 hi/lo split of E (this thread's row = tid).
    uint32_t Ehp[25], Elp[25];
#pragma unroll
    for (int p = 0; p < NE / 2; ++p) {
        float e0 = tanhf(lo32(eacc[p]) + __ldg(Eb + 2 * p));
        float e1 = tanhf(hi32(eacc[p]) + __ldg(Eb + 2 * p + 1));
        __nv_bfloat162 h2 = __floats2bfloat162_rn(e0, e1);
        uint32_t hv; memcpy(&hv, &h2, 4);
        float r0 = e0 - __bfloat162float(__low2bfloat16(h2));
        float r1 = e1 - __bfloat162float(__high2bfloat16(h2));
        Ehp[p] = hv;
        Elp[p] = pack_bf16(r0, r1);
    }
    const uint32_t one2 = pack_bf16(1.0f, 1.0f);

    // ---- Build A fragments via warp shuffle (rows of warp wid == its lanes).
    // A frag (s,ks): reg0 row s*16+g   cols ks*16+tig*2
    //               reg1 row s*16+g+8  same cols
    //               reg2 row s*16+g    cols +8, reg3 row +8 cols +8
    uint32_t Af[2][KSTEPS][4];
#pragma unroll
    for (int s = 0; s < 2; ++s) {
#pragma unroll
        for (int ks = 0; ks < KSTEPS; ++ks) {
#pragma unroll
            for (int t = 0; t < 4; ++t) {
                uint32_t v0 = colsel(Ehp, Elp, one2, 8 * ks + t);
                uint32_t v1 = colsel(Ehp, Elp, one2, 8 * ks + 4 + t);
                uint32_t r0 = __shfl_sync(0xffffffffu, v0, s * 16 + g);
                uint32_t r1 = __shfl_sync(0xffffffffu, v0, s * 16 + g + 8);
                uint32_t r2 = __shfl_sync(0xffffffffu, v1, s * 16 + g);
                uint32_t r3 = __shfl_sync(0xffffffffu, v1, s * 16 + g + 8);
                if (tig == t) {
                    Af[s][ks][0] = r0; Af[s][ks][1] = r1;
                    Af[s][ks][2] = r2; Af[s][ks][3] = r3;
                }
            }
        }
    }

    // ---------------- Main loop: 33 iterations of 40 columns ----------------
#pragma unroll 1
    for (int c = 0; c < NITER; ++c) {
        CP_WAIT1();
        __syncthreads();         // B buffer (c&1) visible to all warps

        const uint32_t* bbuf =
            reinterpret_cast<const uint32_t*>(smem + ((c & 1) ? OFF_B1 : OFF_B0));

        float C[2][NCHUNKS][4];
#pragma unroll
        for (int s = 0; s < 2; ++s)
#pragma unroll
            for (int ch = 0; ch < NCHUNKS; ++ch)
#pragma unroll
                for (int q = 0; q < 4; ++q) C[s][ch][q] = 0.0f;

#pragma unroll
        for (int ch = 0; ch < NCHUNKS; ++ch) {
#pragma unroll
            for (int ks = 0; ks < KSTEPS; ++ks) {
                uint2 bv = *reinterpret_cast<const uint2*>(
                    bbuf + (ch * KSTEPS + ks) * 64 + lid * 2);
                mma16816(C[0][ch], Af[0][ks], bv.x, bv.y);
                mma16816(C[1][ch], Af[1][ks], bv.x, bv.y);
            }
        }
        __syncthreads();         // all warps done reading buffer (c&1)

        if (c + 2 < NITER) {     // refill freed buffer with iter c+2
            const unsigned char* src = bg + (size_t)(c + 2) * BITER;
            for (int j = tid; j < BITER / 16; j += THREADS)
                cp16(smem + ((c & 1) ? OFF_B1 : OFF_B0) + j * 16, src + j * 16);
        }
        CP_COMMIT();

        // ---- Softmax in registers + x update (no smem staging) ------------
        // Feature i0=2c: cols 0-19 (ch0,ch1, ch2@tig<2). i1=2c+1: cols 20-39.
#pragma unroll
        for (int s = 0; s < 2; ++s) {
            float ex[NCHUNKS][4];
#pragma unroll
            for (int ch = 0; ch < NCHUNKS; ++ch)
#pragma unroll
                for (int q = 0; q < 4; ++q) ex[ch][q] = __expf(C[s][ch][q]);

            float p00 = ex[0][0] + ex[0][1] + ex[1][0] + ex[1][1];  // f0, row g
            float p01 = ex[0][2] + ex[0][3] + ex[1][2] + ex[1][3];  // f0, row g+8
            float p10 = ex[3][0] + ex[3][1] + ex[4][0] + ex[4][1];  // f1, row g
            float p11 = ex[3][2] + ex[3][3] + ex[4][2] + ex[4][3];  // f1, row g+8
            if (tig < 2) { p00 += ex[2][0] + ex[2][1]; p01 += ex[2][2] + ex[2][3]; }
            else         { p10 += ex[2][0] + ex[2][1]; p11 += ex[2][2] + ex[2][3]; }

            p00 += __shfl_xor_sync(0xffffffffu, p00, 1);
            p00 += __shfl_xor_sync(0xffffffffu, p00, 2);
            p01 += __shfl_xor_sync(0xffffffffu, p01, 1);
            p01 += __shfl_xor_sync(0xffffffffu, p01, 2);
            p10 += __shfl_xor_sync(0xffffffffu, p10, 1);
            p10 += __shfl_xor_sync(0xffffffffu, p10, 2);
            p11 += __shfl_xor_sync(0xffffffffu, p11, 1);
            p11 += __shfl_xor_sync(0xffffffffu, p11, 2);

            int row0 = wid * 32 + s * 16 + g;
            int row1 = row0 + 8;
            if (tig == 0) {      // class-1 of f0 = col 1 -> ch0 reg1/reg3
                x_sh[row0 * XPITCH + 2 * c] *= ex[0][1] * __fdividef(1.0f, p00);
                x_sh[row1 * XPITCH + 2 * c] *= ex[0][3] * __fdividef(1.0f, p01);
            } else if (tig == 2) { // class-1 of f1 = col 21 -> ch2 reg1/reg3
                x_sh[row0 * XPITCH + 2 * c + 1] *= ex[2][1] * __fdividef(1.0f, p10);
                x_sh[row1 * XPITCH + 2 * c + 1] *= ex[2][3] * __fdividef(1.0f, p11);
            }
        }
    }
    __syncthreads();

    // Coalesced writeback.
    float* og = out + base * NIN;
    for (int idx = tid; idx < MTILE * NIN; idx += THREADS)
        og[idx] = x_sh[(idx / NIN) * XPITCH + (idx % NIN)];
}

// ---------------------------------------------------------------------------
extern "C" void kernel_launch(void* const* d_in, const int* in_sizes, int n_in,
                              void* d_out, int out_size) {
    const float* x  = (const float*)d_in[0];
    const float* EW = (const float*)d_in[1];
    const float* Eb = (const float*)d_in[2];
    const float* AW = (const float*)d_in[3];
    const float* Ab = (const float*)d_in[4];
    float* out = (float*)d_out;

    int prep_elems = NITER * NCHUNKS * KSTEPS * 64;
    prep_kernel<<<(prep_elems + 255) / 256, 256>>>(AW, Ab);

    cudaFuncSetAttribute(attn_mma,
                         cudaFuncAttributeMaxDynamicSharedMemorySize, SMEM_BYTES);
    attn_mma<<<B_TOTAL / MTILE, THREADS, SMEM_BYTES>>>(x, EW, Eb, out);
}